// round 2
// baseline (speedup 1.0000x reference)
#include <cuda_runtime.h>
#include <math.h>

// ---------------------------------------------------------------------------
// Problem constants (fixed by setup_inputs)
// ---------------------------------------------------------------------------
#define MINST 156          // number of prefix instances (N - num_obs)
#define NTOK  256          // sequence length
#define DM    256          // d_model
#define DFF   1024         // feedforward dim
#define NHEAD 8
#define DHEAD 32
#define RTOT  (MINST*NTOK) // 39936 flattened rows
#define NOBS  100
#define NLAYER 4

// ---------------------------------------------------------------------------
// Device-global scratch (no cudaMalloc allowed)
// ---------------------------------------------------------------------------
__device__ float g_X [(size_t)RTOT*DM];   // activations
__device__ float g_Qb[(size_t)RTOT*DM];
__device__ float g_Kb[(size_t)RTOT*DM];
__device__ float g_Vb[(size_t)RTOT*DM];
__device__ float g_Ob[(size_t)RTOT*DM];   // attention output
__device__ float g_Pb[(size_t)RTOT*DM];   // projection / ffn2 output
__device__ float g_Hb[(size_t)RTOT*DFF];  // ffn hidden
__device__ float g_x0[NTOK*DM];           // enc_input + positional encoding
__device__ float g_bias[NTOK];            // key-padding additive bias (0 / -1e9)

// ---------------------------------------------------------------------------
// Init: positional encoding  x0 = enc + PE
// PE[pos, c] = (c even ? sin : cos)(pos * 10000^(-2c/d))
// (faithful to the reference's non-standard exponents)
// ---------------------------------------------------------------------------
__global__ void init_x0_kernel(const float* __restrict__ enc)
{
    int pos = blockIdx.x;
    int c   = threadIdx.x;
    float ang = (float)pos * powf(10000.f, -(float)c / 128.f); // 2c/256 = c/128
    float pe  = (c & 1) ? cosf(ang) : sinf(ang);
    g_x0[pos*DM + c] = enc[pos*DM + c] + pe;
}

// ---------------------------------------------------------------------------
// Init: decode mask (auto-detect bool8 / int32 / float32 serialization)
// and build additive bias vector.
// ---------------------------------------------------------------------------
__global__ void init_bias_kernel(const unsigned char* __restrict__ m)
{
    __shared__ int notf32, noti32, anynz;
    int t = threadIdx.x; // 256 threads
    if (t == 0) { notf32 = 0; noti32 = 0; anynz = 0; }
    __syncthreads();
    if (t < 64) {
        unsigned int w = ((const unsigned int*)m)[t]; // first 256 bytes only
        if (w != 0u && w != 0x3f800000u) atomicOr(&notf32, 1);
        if (w != 0u && w != 1u)          atomicOr(&noti32, 1);
    }
    if (m[t]) atomicOr(&anynz, 1);
    __syncthreads();
    bool mv;
    if (!anynz)        mv = false;                         // all-zero: any decode
    else if (!notf32)  mv = ((const float*)m)[t] != 0.f;   // float32-encoded
    else if (!noti32)  mv = ((const int*)m)[t]   != 0;     // int32-encoded
    else               mv = m[t] != 0;                     // bool8
    g_bias[t] = mv ? 0.f : -1e9f;
}

// ---------------------------------------------------------------------------
// Replicate x0 into all MINST instances
// ---------------------------------------------------------------------------
__global__ void replicate_kernel()
{
    int m = blockIdx.y, pos = blockIdx.x, c = threadIdx.x;
    g_X[((size_t)m*NTOK + pos)*DM + c] = g_x0[pos*DM + c];
}

// ---------------------------------------------------------------------------
// Tiled fp32 GEMM:  C[R,N] = A[R,K] @ B[K,N] + bias[N]   (optional relu)
// Block tile 128x64, K-tile 16, 256 threads, 8x4 microtile per thread.
// R = RTOT (multiple of 128), K,N in {256,1024} (multiples of 16/64).
// ---------------------------------------------------------------------------
__global__ void __launch_bounds__(256)
gemm_kernel(const float* __restrict__ A, const float* __restrict__ Bw,
            const float* __restrict__ bias, float* __restrict__ C,
            int K, int N, int relu)
{
    __shared__ float As[16][128]; // transposed: As[k][row]
    __shared__ float Bs[16][64];

    const int brow = blockIdx.y << 7;
    const int bcol = blockIdx.x << 6;
    const int tid  = threadIdx.x;
    const int tx   = tid & 15;   // col group (4 cols)
    const int ty   = tid >> 4;   // row group (8 rows)
    const int a_row = tid >> 2;        // 0..63
    const int a_col = (tid & 3) << 2;  // 0,4,8,12
    const int b_row = tid >> 4;        // 0..15
    const int b_col = (tid & 15) << 2; // 0..60

    const float* Ap0 = A + (size_t)(brow + a_row) * K + a_col;
    const float* Ap1 = Ap0 + (size_t)64 * K;
    const float* Bp  = Bw + (size_t)b_row * N + bcol + b_col;

    float acc[8][4];
#pragma unroll
    for (int i = 0; i < 8; i++)
#pragma unroll
        for (int j = 0; j < 4; j++) acc[i][j] = 0.f;

    for (int k0 = 0; k0 < K; k0 += 16) {
        float4 a0 = *(const float4*)(Ap0 + k0);
        float4 a1 = *(const float4*)(Ap1 + k0);
        float4 bv = *(const float4*)(Bp + (size_t)k0 * N);
        As[a_col+0][a_row]    = a0.x; As[a_col+1][a_row]    = a0.y;
        As[a_col+2][a_row]    = a0.z; As[a_col+3][a_row]    = a0.w;
        As[a_col+0][a_row+64] = a1.x; As[a_col+1][a_row+64] = a1.y;
        As[a_col+2][a_row+64] = a1.z; As[a_col+3][a_row+64] = a1.w;
        *(float4*)&Bs[b_row][b_col] = bv;
        __syncthreads();
#pragma unroll
        for (int kk = 0; kk < 16; kk++) {
            float4 af0 = *(const float4*)&As[kk][ty << 3];
            float4 af1 = *(const float4*)&As[kk][(ty << 3) + 4];
            float4 bf  = *(const float4*)&Bs[kk][tx << 2];
            float ar[8] = {af0.x, af0.y, af0.z, af0.w, af1.x, af1.y, af1.z, af1.w};
            float br[4] = {bf.x, bf.y, bf.z, bf.w};
#pragma unroll
            for (int i = 0; i < 8; i++)
#pragma unroll
                for (int j = 0; j < 4; j++)
                    acc[i][j] = fmaf(ar[i], br[j], acc[i][j]);
        }
        __syncthreads();
    }

    float bvals[4];
#pragma unroll
    for (int j = 0; j < 4; j++) bvals[j] = bias[bcol + (tx << 2) + j];
#pragma unroll
    for (int i = 0; i < 8; i++) {
        float* crow = C + (size_t)(brow + (ty << 3) + i) * N + bcol + (tx << 2);
        float4 v;
        v.x = acc[i][0] + bvals[0];
        v.y = acc[i][1] + bvals[1];
        v.z = acc[i][2] + bvals[2];
        v.w = acc[i][3] + bvals[3];
        if (relu) {
            v.x = fmaxf(v.x, 0.f); v.y = fmaxf(v.y, 0.f);
            v.z = fmaxf(v.z, 0.f); v.w = fmaxf(v.w, 0.f);
        }
        *(float4*)crow = v;
    }
}

// ---------------------------------------------------------------------------
// Attention: one block per (head, instance). K/V tiles resident in smem
// (2 * 256*32 * 4B = 64 KB dynamic). One query row per thread, streaming
// online softmax with prefix mask p = NOBS + m plus key-padding bias.
// ---------------------------------------------------------------------------
__global__ void __launch_bounds__(256)
attn_kernel(const float* __restrict__ Q, const float* __restrict__ K,
            const float* __restrict__ V, float* __restrict__ O)
{
    extern __shared__ float sh[];
    float* Ks = sh;               // [256*32]
    float* Vs = sh + NTOK * DHEAD;

    const int h = blockIdx.x;
    const int m = blockIdx.y;
    const int p = NOBS + m;       // keys j < p are visible (subject to pad mask)
    const int t = threadIdx.x;
    const size_t base = (size_t)m * NTOK * DM + (size_t)h * DHEAD;

    // cooperative coalesced K/V load: warp reads one 128B row segment
#pragma unroll
    for (int i = 0; i < 32; i++) {
        int flat = (i << 8) + t;          // 0..8191
        int j = flat >> 5, c = flat & 31;
        size_t g = base + (size_t)j * DM + c;
        Ks[flat] = K[g];
        Vs[flat] = V[g];
    }

    float q[DHEAD];
#pragma unroll
    for (int c = 0; c < DHEAD; c += 4) {
        float4 qv = *(const float4*)&Q[base + (size_t)t * DM + c];
        q[c] = qv.x; q[c+1] = qv.y; q[c+2] = qv.z; q[c+3] = qv.w;
    }
    __syncthreads();

    float mx = -INFINITY, sm = 0.f;
    float acc[DHEAD];
#pragma unroll
    for (int c = 0; c < DHEAD; c++) acc[c] = 0.f;
    const float scale = 0.17677669529663687f; // 1/sqrt(32)

    for (int j = 0; j < NTOK; j++) {
        const float* kp = Ks + (j << 5);
        float s0 = 0.f, s1 = 0.f, s2 = 0.f, s3 = 0.f;
#pragma unroll
        for (int c = 0; c < DHEAD; c += 4) {
            s0 = fmaf(q[c  ], kp[c  ], s0);
            s1 = fmaf(q[c+1], kp[c+1], s1);
            s2 = fmaf(q[c+2], kp[c+2], s2);
            s3 = fmaf(q[c+3], kp[c+3], s3);
        }
        float s = ((s0 + s1) + (s2 + s3)) * scale
                + ((j < p) ? g_bias[j] : -1e9f);
        const float* vp = Vs + (j << 5);
        if (s > mx) {
            float corr = expf(mx - s);   // expf(-inf)=0 handles first iter
            sm = sm * corr + 1.f;
#pragma unroll
            for (int c = 0; c < DHEAD; c++) acc[c] = fmaf(acc[c], corr, vp[c]);
            mx = s;
        } else {
            float ps = expf(s - mx);     // masked keys -> exp(~-1e9) = 0
            sm += ps;
#pragma unroll
            for (int c = 0; c < DHEAD; c++) acc[c] = fmaf(ps, vp[c], acc[c]);
        }
    }

    float inv = 1.f / sm;
#pragma unroll
    for (int c = 0; c < DHEAD; c += 4) {
        float4 o4 = make_float4(acc[c]*inv, acc[c+1]*inv, acc[c+2]*inv, acc[c+3]*inv);
        *(float4*)&O[base + (size_t)t * DM + c] = o4;
    }
}

// ---------------------------------------------------------------------------
// X = LayerNorm(X + P) * scale + bias    (warp per row, 8 rows per block)
// ---------------------------------------------------------------------------
__global__ void __launch_bounds__(256)
add_ln_kernel(float* __restrict__ X, const float* __restrict__ P,
              const float* __restrict__ sc, const float* __restrict__ bi)
{
    int r    = blockIdx.x * 8 + (threadIdx.x >> 5);
    int lane = threadIdx.x & 31;
    float*       xr = X + (size_t)r * DM;
    const float* pr = P + (size_t)r * DM;

    float v[8]; float sum = 0.f;
#pragma unroll
    for (int k = 0; k < 8; k++) {
        int c = lane + (k << 5);
        v[k] = xr[c] + pr[c];
        sum += v[k];
    }
#pragma unroll
    for (int o = 16; o; o >>= 1) sum += __shfl_xor_sync(0xffffffffu, sum, o);
    float mu = sum * (1.f / 256.f);

    float sq = 0.f;
#pragma unroll
    for (int k = 0; k < 8; k++) { float d = v[k] - mu; sq = fmaf(d, d, sq); }
#pragma unroll
    for (int o = 16; o; o >>= 1) sq += __shfl_xor_sync(0xffffffffu, sq, o);

    float inv = rsqrtf(sq * (1.f / 256.f) + 1e-5f);
#pragma unroll
    for (int k = 0; k < 8; k++) {
        int c = lane + (k << 5);
        xr[c] = (v[k] - mu) * inv * sc[c] + bi[c];
    }
}

// ---------------------------------------------------------------------------
// Gather final embeddings: out[m, :] = X[m, (NOBS-1)+m, :]
// ---------------------------------------------------------------------------
__global__ void gather_kernel(const float* __restrict__ X, float* __restrict__ out)
{
    int m = blockIdx.x, c = threadIdx.x;
    out[(size_t)m * DM + c] = X[((size_t)m * NTOK + (NOBS - 1 + m)) * DM + c];
}

// ---------------------------------------------------------------------------
// Launch
// ---------------------------------------------------------------------------
extern "C" void kernel_launch(void* const* d_in, const int* in_sizes, int n_in,
                              void* d_out, int out_size)
{
    (void)in_sizes; (void)n_in; (void)out_size;
    const float* enc = (const float*)d_in[0];
    const unsigned char* mask = (const unsigned char*)d_in[1];
    const float* Wq = (const float*)d_in[2];
    const float* bq = (const float*)d_in[3];
    const float* Wk = (const float*)d_in[4];
    const float* bk = (const float*)d_in[5];
    const float* Wv = (const float*)d_in[6];
    const float* bv = (const float*)d_in[7];
    const float* Wo = (const float*)d_in[8];
    const float* bo = (const float*)d_in[9];
    const float* l1s = (const float*)d_in[10];
    const float* l1b = (const float*)d_in[11];
    const float* l2s = (const float*)d_in[12];
    const float* l2b = (const float*)d_in[13];
    const float* W1 = (const float*)d_in[14];
    const float* b1 = (const float*)d_in[15];
    const float* W2 = (const float*)d_in[16];
    const float* b2 = (const float*)d_in[17];
    float* out = (float*)d_out;

    float *X, *Qp, *Kp, *Vp, *Op, *Pp, *Hp;
    cudaGetSymbolAddress((void**)&X,  g_X);
    cudaGetSymbolAddress((void**)&Qp, g_Qb);
    cudaGetSymbolAddress((void**)&Kp, g_Kb);
    cudaGetSymbolAddress((void**)&Vp, g_Vb);
    cudaGetSymbolAddress((void**)&Op, g_Ob);
    cudaGetSymbolAddress((void**)&Pp, g_Pb);
    cudaGetSymbolAddress((void**)&Hp, g_Hb);

    cudaFuncSetAttribute(attn_kernel,
                         cudaFuncAttributeMaxDynamicSharedMemorySize, 65536);

    init_bias_kernel<<<1, 256>>>(mask);
    init_x0_kernel<<<NTOK, DM>>>(enc);
    replicate_kernel<<<dim3(NTOK, MINST), DM>>>();

    const dim3 gemm_d (DM  / 64, RTOT / 128); // N=256 outputs
    const dim3 gemm_ff(DFF / 64, RTOT / 128); // N=1024 outputs

    for (int l = 0; l < NLAYER; l++) {
        const float* wq = Wq + (size_t)l * DM * DM;
        const float* wk = Wk + (size_t)l * DM * DM;
        const float* wv = Wv + (size_t)l * DM * DM;
        const float* wo = Wo + (size_t)l * DM * DM;
        const float* w1 = W1 + (size_t)l * DM * DFF;
        const float* w2 = W2 + (size_t)l * DFF * DM;

        gemm_kernel<<<gemm_d, 256>>>(X, wq, bq + l*DM, Qp, DM, DM, 0);
        gemm_kernel<<<gemm_d, 256>>>(X, wk, bk + l*DM, Kp, DM, DM, 0);
        gemm_kernel<<<gemm_d, 256>>>(X, wv, bv + l*DM, Vp, DM, DM, 0);

        attn_kernel<<<dim3(NHEAD, MINST), 256, 65536>>>(Qp, Kp, Vp, Op);

        gemm_kernel<<<gemm_d, 256>>>(Op, wo, bo + l*DM, Pp, DM, DM, 0);
        add_ln_kernel<<<RTOT / 8, 256>>>(X, Pp, l1s + l*DM, l1b + l*DM);

        gemm_kernel<<<gemm_ff, 256>>>(X, w1, b1 + l*DFF, Hp, DM, DFF, 1);
        gemm_kernel<<<gemm_d, 256>>>(Hp, w2, b2 + l*DM, Pp, DFF, DM, 0);
        add_ln_kernel<<<RTOT / 8, 256>>>(X, Pp, l2s + l*DM, l2b + l*DM);
    }

    gather_kernel<<<MINST, DM>>>(X, out);
}

// round 4
// speedup vs baseline: 2.5819x; 2.5819x over previous
#include <cuda_runtime.h>
#include <cuda_bf16.h>
#include <math.h>
#include <stdint.h>

// ---------------------------------------------------------------------------
// Problem constants
// ---------------------------------------------------------------------------
#define MINST 156
#define NTOK  256
#define DM    256
#define DFF   1024
#define NHEAD 8
#define DHEAD 32
#define NOBS  100
#define NLAYER 4

// Packed (truncated) rows: instance m keeps p = NOBS+m rows.
// RSUM = sum_m (100+m) = 27690 ; padded to 128-multiple:
#define RSUM 27690
#define RP   27776            // 217 * 128

#define KE_DM  (3*DM)        // 768
#define KE_FF  (3*DFF)       // 3072
#define QKVW   (3*DM)        // 768 fused QKV output width

__device__ __forceinline__ int inst_off(int m) {
    return NOBS*m + (m*(m-1))/2;
}

// ---------------------------------------------------------------------------
// Device-global scratch
// ---------------------------------------------------------------------------
__device__ float g_X [(size_t)RP*DM];                 // fp32 residual stream (packed)
__device__ __nv_bfloat16 g_Xeff[(size_t)RP*KE_DM];    // [hi|hi|lo] of X
__device__ float g_QKV[(size_t)RP*QKVW];              // fused Q|K|V fp32
__device__ __nv_bfloat16 g_Oeff[(size_t)RP*KE_DM];    // attention out, expanded
__device__ float g_P[(size_t)RP*DM];                  // proj / ffn2 output
__device__ __nv_bfloat16 g_Heff[(size_t)RP*KE_FF];    // ffn hidden, expanded
__device__ float g_x0[NTOK*DM];
__device__ float g_bias[NTOK];
__device__ float g_bqkv[NLAYER*QKVW];

// Expanded weights: [N][3K] bf16 rows = output col, K-major [hi|lo|hi]
__device__ __nv_bfloat16 g_WqkvE[NLAYER*(size_t)QKVW*KE_DM];
__device__ __nv_bfloat16 g_WoE[NLAYER*(size_t)DM*KE_DM];
__device__ __nv_bfloat16 g_W1E[NLAYER*(size_t)DFF*KE_DM];
__device__ __nv_bfloat16 g_W2E[NLAYER*(size_t)DM*KE_FF];

// ---------------------------------------------------------------------------
// PTX helpers (base sm_100 target — NO 'a'-gated instructions)
// ---------------------------------------------------------------------------
__device__ __forceinline__ uint32_t smem_u32(const void* p) {
    uint32_t a;
    asm("{ .reg .u64 t; cvta.to.shared.u64 t, %1; cvt.u32.u64 %0, t; }"
        : "=r"(a) : "l"(p));
    return a;
}
__device__ __forceinline__ void cpa16(uint32_t sts, const void* g) {
    asm volatile("cp.async.cg.shared.global [%0], [%1], 16;" :: "r"(sts), "l"(g));
}
__device__ __forceinline__ void cpa_commit() {
    asm volatile("cp.async.commit_group;" ::: "memory");
}
template <int N> __device__ __forceinline__ void cpa_wait() {
    asm volatile("cp.async.wait_group %0;" :: "n"(N) : "memory");
}
__device__ __forceinline__ void ldm4(uint32_t* r, uint32_t a) {
    asm volatile("ldmatrix.sync.aligned.m8n8.x4.shared.b16 {%0,%1,%2,%3}, [%4];"
        : "=r"(r[0]), "=r"(r[1]), "=r"(r[2]), "=r"(r[3]) : "r"(a));
}
__device__ __forceinline__ void mma16816(float* d, const uint32_t* a,
                                         uint32_t b0, uint32_t b1) {
    asm volatile(
        "mma.sync.aligned.m16n8k16.row.col.f32.bf16.bf16.f32 "
        "{%0,%1,%2,%3}, {%4,%5,%6,%7}, {%8,%9}, {%0,%1,%2,%3};"
        : "+f"(d[0]), "+f"(d[1]), "+f"(d[2]), "+f"(d[3])
        : "r"(a[0]), "r"(a[1]), "r"(a[2]), "r"(a[3]), "r"(b0), "r"(b1));
}
__device__ __forceinline__ void split3(float v, __nv_bfloat16& hi, __nv_bfloat16& lo) {
    hi = __float2bfloat16(v);
    lo = __float2bfloat16(v - __bfloat162float(hi));
}

// ---------------------------------------------------------------------------
// Init kernels
// ---------------------------------------------------------------------------
__global__ void init_x0_kernel(const float* __restrict__ enc)
{
    int pos = blockIdx.x, c = threadIdx.x;
    float ang = (float)pos * powf(10000.f, -(float)c / 128.f);
    float pe  = (c & 1) ? cosf(ang) : sinf(ang);
    g_x0[pos*DM + c] = enc[pos*DM + c] + pe;
}

__global__ void init_bias_kernel(const unsigned char* __restrict__ m)
{
    __shared__ int notf32, noti32, anynz;
    int t = threadIdx.x;
    if (t == 0) { notf32 = 0; noti32 = 0; anynz = 0; }
    __syncthreads();
    if (t < 64) {
        unsigned int w = ((const unsigned int*)m)[t];
        if (w != 0u && w != 0x3f800000u) atomicOr(&notf32, 1);
        if (w != 0u && w != 1u)          atomicOr(&noti32, 1);
    }
    if (m[t]) atomicOr(&anynz, 1);
    __syncthreads();
    bool mv;
    if (!anynz)        mv = false;
    else if (!notf32)  mv = ((const float*)m)[t] != 0.f;
    else if (!noti32)  mv = ((const int*)m)[t]   != 0;
    else               mv = m[t] != 0;
    g_bias[t] = mv ? 0.f : -1e9f;
}

__global__ void concat_bias_kernel(const float* __restrict__ bq,
                                   const float* __restrict__ bk,
                                   const float* __restrict__ bv)
{
    int l = blockIdx.x, c = threadIdx.x;
    g_bqkv[l*QKVW + c]          = bq[l*DM + c];
    g_bqkv[l*QKVW + DM + c]     = bk[l*DM + c];
    g_bqkv[l*QKVW + 2*DM + c]   = bv[l*DM + c];
}

// Replicate x0 into packed fp32 X and bf16x3 Xeff (rows pos < p only)
__global__ void replicate_kernel()
{
    int m = blockIdx.y, pos = blockIdx.x, c = threadIdx.x;
    if (pos >= NOBS + m) return;
    size_t r = (size_t)inst_off(m) + pos;
    float v = g_x0[pos*DM + c];
    g_X[r*DM + c] = v;
    __nv_bfloat16 hi, lo; split3(v, hi, lo);
    size_t rb = r*KE_DM;
    g_Xeff[rb + c] = hi; g_Xeff[rb + DM + c] = hi; g_Xeff[rb + 2*DM + c] = lo;
}

// Weight conversion: W[K,N] fp32 -> out[N][3K] bf16 as [hi|lo|hi]
__global__ void convw_kernel(const float* __restrict__ W,
                             __nv_bfloat16* __restrict__ out, int K, int N)
{
    __shared__ float t[32][33];
    int n0 = blockIdx.x*32, k0 = blockIdx.y*32;
    int tx = threadIdx.x, ty = threadIdx.y;   // 32 x 8
#pragma unroll
    for (int i = 0; i < 32; i += 8)
        t[ty+i][tx] = W[(size_t)(k0+ty+i)*N + n0+tx];
    __syncthreads();
#pragma unroll
    for (int i = 0; i < 32; i += 8) {
        int n = n0+ty+i, k = k0+tx;
        float v = t[tx][ty+i];
        __nv_bfloat16 hi, lo; split3(v, hi, lo);
        size_t base = (size_t)n*3*K;
        out[base + k] = hi; out[base + K + k] = lo; out[base + 2*K + k] = hi;
    }
}

// ---------------------------------------------------------------------------
// bf16 mma.sync GEMM:  C[RP,N] = A[RP,KT] . B[N,KT]^T  (+bias per col)
// BM=128, BN=128, BK=64, 3-stage cp.async, 256 thr = 8 warps (2x4),
// warp tile 64x32, HMMA m16n8k16.
// mode 0: fp32 out + bias.  mode 1: relu(out+bias) -> bf16x3 [hi|hi|lo].
// ---------------------------------------------------------------------------
#define BM 128
#define BN 128
#define BK 64
#define STAGE_BYTES (BM*BK*2 + BN*BK*2)   // 32768
#define GSMEM_TOTAL (3*STAGE_BYTES)       // 98304

__global__ void __launch_bounds__(256)
gemm_tc_kernel(const __nv_bfloat16* __restrict__ A,
               const __nv_bfloat16* __restrict__ B,
               const float* __restrict__ bias,
               float* __restrict__ outF, __nv_bfloat16* __restrict__ outE,
               int KT, int N, int mode)
{
    extern __shared__ __align__(128) char smem[];
    const uint32_t sb = smem_u32(smem);
    const int tid  = threadIdx.x;
    const int lane = tid & 31, wid = tid >> 5;
    const int wm = wid & 1, wn = wid >> 1;        // 2 x 4 warp grid
    const int brow = blockIdx.y * BM;
    const int bcol = blockIdx.x * BN;
    const int KC = KT / BK;
    const int lr = lane & 7, quad = lane >> 3;

    float acc[4][4][4];
#pragma unroll
    for (int a = 0; a < 4; a++)
#pragma unroll
        for (int b = 0; b < 4; b++)
#pragma unroll
            for (int c = 0; c < 4; c++) acc[a][b][c] = 0.f;

    auto load_tile = [&](int i, int st) {
        const uint32_t sa = sb + st*STAGE_BYTES;
        const uint32_t sB = sa + BM*BK*2;
        const int k0 = i * BK;
#pragma unroll
        for (int it = 0; it < 4; it++) {
            int id = it*256 + tid, r = id >> 3, c = id & 7;
            uint32_t sw = r*128 + ((c ^ (r & 7)) << 4);
            cpa16(sa + sw, A + (size_t)(brow + r)*KT + k0 + c*8);
        }
#pragma unroll
        for (int it = 0; it < 4; it++) {
            int id = it*256 + tid, r = id >> 3, c = id & 7;
            uint32_t sw = r*128 + ((c ^ (r & 7)) << 4);
            cpa16(sB + sw, B + (size_t)(bcol + r)*KT + k0 + c*8);
        }
        cpa_commit();
    };

    load_tile(0, 0);
    load_tile(1, 1);

    // precomputed ldmatrix row indices
    int rowA[4], rowB[2];
#pragma unroll
    for (int mt = 0; mt < 4; mt++)
        rowA[mt] = wm*64 + mt*16 + lr + ((quad & 1) << 3);
#pragma unroll
    for (int bt = 0; bt < 2; bt++)
        rowB[bt] = wn*32 + bt*16 + lr + ((quad & 2) << 2);
    const int chA = (quad & 2) >> 1;  // k-half for A
    const int chB = (quad & 1);       // k-half for B

    for (int i = 0; i < KC; i++) {
        if (i + 1 < KC) cpa_wait<1>(); else cpa_wait<0>();
        __syncthreads();
        const uint32_t sa = sb + (i % 3)*STAGE_BYTES;
        const uint32_t sB = sa + BM*BK*2;
#pragma unroll
        for (int ks = 0; ks < 4; ks++) {
            uint32_t af[4][4];
#pragma unroll
            for (int mt = 0; mt < 4; mt++) {
                int ch = ks*2 + chA;
                ldm4(af[mt], sa + rowA[mt]*128 + ((ch ^ (rowA[mt] & 7)) << 4));
            }
            uint32_t bf[2][4];
#pragma unroll
            for (int bt = 0; bt < 2; bt++) {
                int ch = ks*2 + chB;
                ldm4(bf[bt], sB + rowB[bt]*128 + ((ch ^ (rowB[bt] & 7)) << 4));
            }
#pragma unroll
            for (int mt = 0; mt < 4; mt++)
#pragma unroll
                for (int nt = 0; nt < 4; nt++)
                    mma16816(acc[mt][nt], af[mt],
                             bf[nt >> 1][(nt & 1)*2], bf[nt >> 1][(nt & 1)*2 + 1]);
        }
        if (i + 2 < KC) load_tile(i + 2, (i + 2) % 3);
    }

    // ---- epilogue ----
    const int r0 = brow + wm*64 + (lane >> 2);
    const int c0 = bcol + wn*32 + ((lane & 3) << 1);
#pragma unroll
    for (int mt = 0; mt < 4; mt++) {
#pragma unroll
        for (int nt = 0; nt < 4; nt++) {
            int row = r0 + mt*16;
            int col = c0 + nt*8;
            float bv0 = bias[col], bv1 = bias[col + 1];
            float v00 = acc[mt][nt][0] + bv0, v01 = acc[mt][nt][1] + bv1;
            float v10 = acc[mt][nt][2] + bv0, v11 = acc[mt][nt][3] + bv1;
            if (mode == 0) {
                *(float2*)&outF[(size_t)row*N + col]     = make_float2(v00, v01);
                *(float2*)&outF[(size_t)(row+8)*N + col] = make_float2(v10, v11);
            } else {
                v00 = fmaxf(v00, 0.f); v01 = fmaxf(v01, 0.f);
                v10 = fmaxf(v10, 0.f); v11 = fmaxf(v11, 0.f);
                __nv_bfloat16 h0, l0, h1, l1;
                split3(v00, h0, l0); split3(v01, h1, l1);
                __nv_bfloat162 hp = __halves2bfloat162(h0, h1);
                __nv_bfloat162 lp = __halves2bfloat162(l0, l1);
                size_t rb = (size_t)row * (3*N);
                *(__nv_bfloat162*)&outE[rb + col]       = hp;
                *(__nv_bfloat162*)&outE[rb + N + col]   = hp;
                *(__nv_bfloat162*)&outE[rb + 2*N + col] = lp;
                split3(v10, h0, l0); split3(v11, h1, l1);
                hp = __halves2bfloat162(h0, h1);
                lp = __halves2bfloat162(l0, l1);
                rb = (size_t)(row+8) * (3*N);
                *(__nv_bfloat162*)&outE[rb + col]       = hp;
                *(__nv_bfloat162*)&outE[rb + N + col]   = hp;
                *(__nv_bfloat162*)&outE[rb + 2*N + col] = lp;
            }
        }
    }
}

// ---------------------------------------------------------------------------
// Attention over packed rows; fused QKV input (row stride 768).
// Block per (head, instance); queries/keys truncated to < p.
// Writes Oeff directly in bf16x3 form.
// ---------------------------------------------------------------------------
__global__ void __launch_bounds__(256)
attn_kernel(const float* __restrict__ QKV, __nv_bfloat16* __restrict__ Oe)
{
    extern __shared__ float sh[];
    float* Ks = sh;               // [256*32]
    float* Vs = sh + NTOK * DHEAD;

    const int h = blockIdx.x;
    const int m = blockIdx.y;
    const int p = NOBS + m;
    const int t = threadIdx.x;
    const int off = inst_off(m);

    for (int flat = t; flat < p*DHEAD; flat += 256) {
        int j = flat >> 5, c = flat & 31;
        size_t g = (size_t)(off + j)*QKVW + h*DHEAD + c;
        Ks[flat] = QKV[g + DM];
        Vs[flat] = QKV[g + 2*DM];
    }

    float q[DHEAD];
    if (t < p) {
        size_t qb = (size_t)(off + t)*QKVW + h*DHEAD;
#pragma unroll
        for (int c = 0; c < DHEAD; c += 4) {
            float4 qv = *(const float4*)&QKV[qb + c];
            q[c] = qv.x; q[c+1] = qv.y; q[c+2] = qv.z; q[c+3] = qv.w;
        }
    }
    __syncthreads();
    if (t >= p) return;

    float mx = -INFINITY, sm = 0.f;
    float acc[DHEAD];
#pragma unroll
    for (int c = 0; c < DHEAD; c++) acc[c] = 0.f;
    const float scale = 0.17677669529663687f; // 1/sqrt(32)

    for (int j = 0; j < p; j++) {
        const float* kp = Ks + (j << 5);
        float s0 = 0.f, s1 = 0.f, s2 = 0.f, s3 = 0.f;
#pragma unroll
        for (int c = 0; c < DHEAD; c += 4) {
            s0 = fmaf(q[c  ], kp[c  ], s0);
            s1 = fmaf(q[c+1], kp[c+1], s1);
            s2 = fmaf(q[c+2], kp[c+2], s2);
            s3 = fmaf(q[c+3], kp[c+3], s3);
        }
        float s = ((s0 + s1) + (s2 + s3)) * scale + g_bias[j];
        const float* vp = Vs + (j << 5);
        if (s > mx) {
            float corr = expf(mx - s);
            sm = sm * corr + 1.f;
#pragma unroll
            for (int c = 0; c < DHEAD; c++) acc[c] = fmaf(acc[c], corr, vp[c]);
            mx = s;
        } else {
            float ps = expf(s - mx);
            sm += ps;
#pragma unroll
            for (int c = 0; c < DHEAD; c++) acc[c] = fmaf(ps, vp[c], acc[c]);
        }
    }

    float inv = 1.f / sm;
    size_t rb = (size_t)(off + t) * KE_DM + h*DHEAD;
#pragma unroll
    for (int c = 0; c < DHEAD; c += 2) {
        float v0 = acc[c]*inv, v1 = acc[c+1]*inv;
        __nv_bfloat16 h0, l0, h1, l1;
        split3(v0, h0, l0); split3(v1, h1, l1);
        __nv_bfloat162 hp = __halves2bfloat162(h0, h1);
        __nv_bfloat162 lp = __halves2bfloat162(l0, l1);
        *(__nv_bfloat162*)&Oe[rb + c]        = hp;
        *(__nv_bfloat162*)&Oe[rb + DM + c]   = hp;
        *(__nv_bfloat162*)&Oe[rb + 2*DM + c] = lp;
    }
}

// ---------------------------------------------------------------------------
// X = LayerNorm(X + P); also writes Xeff = bf16x3(X)
// ---------------------------------------------------------------------------
__global__ void __launch_bounds__(256)
add_ln_kernel(float* __restrict__ X, const float* __restrict__ P,
              const float* __restrict__ sc, const float* __restrict__ bi)
{
    int r    = blockIdx.x * 8 + (threadIdx.x >> 5);
    int lane = threadIdx.x & 31;
    float*       xr = X + (size_t)r * DM;
    const float* pr = P + (size_t)r * DM;

    float v[8]; float sum = 0.f;
#pragma unroll
    for (int k = 0; k < 8; k++) {
        int c = lane + (k << 5);
        v[k] = xr[c] + pr[c];
        sum += v[k];
    }
#pragma unroll
    for (int o = 16; o; o >>= 1) sum += __shfl_xor_sync(0xffffffffu, sum, o);
    float mu = sum * (1.f / 256.f);

    float sq = 0.f;
#pragma unroll
    for (int k = 0; k < 8; k++) { float d = v[k] - mu; sq = fmaf(d, d, sq); }
#pragma unroll
    for (int o = 16; o; o >>= 1) sq += __shfl_xor_sync(0xffffffffu, sq, o);

    float inv = rsqrtf(sq * (1.f / 256.f) + 1e-5f);
    size_t rb = (size_t)r * KE_DM;
#pragma unroll
    for (int k = 0; k < 8; k++) {
        int c = lane + (k << 5);
        float y = (v[k] - mu) * inv * sc[c] + bi[c];
        xr[c] = y;
        __nv_bfloat16 hi, lo; split3(y, hi, lo);
        g_Xeff[rb + c] = hi; g_Xeff[rb + DM + c] = hi; g_Xeff[rb + 2*DM + c] = lo;
    }
}

__global__ void gather_kernel(const float* __restrict__ X, float* __restrict__ out)
{
    int m = blockIdx.x, c = threadIdx.x;
    int row = inst_off(m) + NOBS - 1 + m;   // position p-1
    out[(size_t)m * DM + c] = X[(size_t)row * DM + c];
}

// ---------------------------------------------------------------------------
// Launch
// ---------------------------------------------------------------------------
extern "C" void kernel_launch(void* const* d_in, const int* in_sizes, int n_in,
                              void* d_out, int out_size)
{
    (void)in_sizes; (void)n_in; (void)out_size;
    const float* enc = (const float*)d_in[0];
    const unsigned char* mask = (const unsigned char*)d_in[1];
    const float* Wq = (const float*)d_in[2];
    const float* bq = (const float*)d_in[3];
    const float* Wk = (const float*)d_in[4];
    const float* bk = (const float*)d_in[5];
    const float* Wv = (const float*)d_in[6];
    const float* bv = (const float*)d_in[7];
    const float* Wo = (const float*)d_in[8];
    const float* bo = (const float*)d_in[9];
    const float* l1s = (const float*)d_in[10];
    const float* l1b = (const float*)d_in[11];
    const float* l2s = (const float*)d_in[12];
    const float* l2b = (const float*)d_in[13];
    const float* W1 = (const float*)d_in[14];
    const float* b1 = (const float*)d_in[15];
    const float* W2 = (const float*)d_in[16];
    const float* b2 = (const float*)d_in[17];
    float* out = (float*)d_out;

    float *X, *QKVp, *Pp, *bqkv;
    __nv_bfloat16 *Xe, *Oe, *He, *WqkvE, *WoE, *W1E, *W2E;
    cudaGetSymbolAddress((void**)&X,    g_X);
    cudaGetSymbolAddress((void**)&Xe,   g_Xeff);
    cudaGetSymbolAddress((void**)&QKVp, g_QKV);
    cudaGetSymbolAddress((void**)&Oe,   g_Oeff);
    cudaGetSymbolAddress((void**)&Pp,   g_P);
    cudaGetSymbolAddress((void**)&He,   g_Heff);
    cudaGetSymbolAddress((void**)&bqkv, g_bqkv);
    cudaGetSymbolAddress((void**)&WqkvE, g_WqkvE);
    cudaGetSymbolAddress((void**)&WoE,  g_WoE);
    cudaGetSymbolAddress((void**)&W1E,  g_W1E);
    cudaGetSymbolAddress((void**)&W2E,  g_W2E);

    cudaFuncSetAttribute(attn_kernel,
                         cudaFuncAttributeMaxDynamicSharedMemorySize, 65536);
    cudaFuncSetAttribute(gemm_tc_kernel,
                         cudaFuncAttributeMaxDynamicSharedMemorySize, GSMEM_TOTAL);

    init_bias_kernel<<<1, 256>>>(mask);
    init_x0_kernel<<<NTOK, DM>>>(enc);
    concat_bias_kernel<<<NLAYER, DM>>>(bq, bk, bv);
    replicate_kernel<<<dim3(NTOK, MINST), DM>>>();

    // Weight conversion: QKV fused into [768][768] per layer
    dim3 cb(32, 8);
    for (int l = 0; l < NLAYER; l++) {
        __nv_bfloat16* wqkv = WqkvE + (size_t)l*QKVW*KE_DM;
        convw_kernel<<<dim3(DM/32, DM/32), cb>>>(Wq + (size_t)l*DM*DM, wqkv,                          DM, DM);
        convw_kernel<<<dim3(DM/32, DM/32), cb>>>(Wk + (size_t)l*DM*DM, wqkv + (size_t)DM*KE_DM,       DM, DM);
        convw_kernel<<<dim3(DM/32, DM/32), cb>>>(Wv + (size_t)l*DM*DM, wqkv + (size_t)2*DM*KE_DM,     DM, DM);
        convw_kernel<<<dim3(DM/32, DM/32), cb>>>(Wo + (size_t)l*DM*DM, WoE + (size_t)l*DM*KE_DM,      DM, DM);
        convw_kernel<<<dim3(DFF/32, DM/32), cb>>>(W1 + (size_t)l*DM*DFF, W1E + (size_t)l*DFF*KE_DM,   DM, DFF);
        convw_kernel<<<dim3(DM/32, DFF/32), cb>>>(W2 + (size_t)l*DFF*DM, W2E + (size_t)l*DM*KE_FF,    DFF, DM);
    }

    const int RT = RP / BM;                   // 217 row tiles
    const dim3 g_qkv(QKVW/BN, RT);            // (6, 217)
    const dim3 g_d  (DM/BN,   RT);            // (2, 217)
    const dim3 g_ff (DFF/BN,  RT);            // (8, 217)

    for (int l = 0; l < NLAYER; l++) {
        const __nv_bfloat16* wqkv = WqkvE + (size_t)l*QKVW*KE_DM;
        const __nv_bfloat16* woe  = WoE  + (size_t)l*DM*KE_DM;
        const __nv_bfloat16* w1e  = W1E  + (size_t)l*DFF*KE_DM;
        const __nv_bfloat16* w2e  = W2E  + (size_t)l*DM*KE_FF;

        gemm_tc_kernel<<<g_qkv, 256, GSMEM_TOTAL>>>(Xe, wqkv, bqkv + l*QKVW,
                                                    QKVp, nullptr, KE_DM, QKVW, 0);
        attn_kernel<<<dim3(NHEAD, MINST), 256, 65536>>>(QKVp, Oe);

        gemm_tc_kernel<<<g_d, 256, GSMEM_TOTAL>>>(Oe, woe, bo + l*DM,
                                                  Pp, nullptr, KE_DM, DM, 0);
        add_ln_kernel<<<RP/8, 256>>>(X, Pp, l1s + l*DM, l1b + l*DM);

        gemm_tc_kernel<<<g_ff, 256, GSMEM_TOTAL>>>(Xe, w1e, b1 + l*DFF,
                                                   nullptr, He, KE_DM, DFF, 1);
        gemm_tc_kernel<<<g_d, 256, GSMEM_TOTAL>>>(He, w2e, b2 + l*DM,
                                                  Pp, nullptr, KE_FF, DM, 0);
        add_ln_kernel<<<RP/8, 256>>>(X, Pp, l2s + l*DM, l2b + l*DM);
    }

    gather_kernel<<<MINST, DM>>>(X, out);
}